// round 1
// baseline (speedup 1.0000x reference)
#include <cuda_runtime.h>
#include <cuda_bf16.h>

#define BB 4
#define CC 16
#define HH 512
#define WW 512
#define KK 16
#define HWHW (HH * WW)            // 262144
#define CHUNK 256
#define NCHUNK (HWHW / CHUNK)     // 1024
#define GRIDX 148
#define NTHREADS 256

// stats layout per (b,k): [0..15] = channel sums, [16] = sum of ||e||^2 over fg, [17] = count
__device__ float g_stats[BB][KK][18];

__global__ void zero_stats_kernel() {
    int i = blockIdx.x * blockDim.x + threadIdx.x;
    if (i < BB * KK * 18) ((float*)g_stats)[i] = 0.0f;
}

__device__ __forceinline__ float warp_sum(float x) {
#pragma unroll
    for (int off = 16; off > 0; off >>= 1)
        x += __shfl_down_sync(0xffffffffu, x, off);
    return x;
}

__global__ __launch_bounds__(NTHREADS)
void stats_kernel(const float* __restrict__ emb, const int* __restrict__ mask) {
    __shared__ float emb_sh[CC][CHUNK];
    __shared__ float s2_sh[CHUNK];

    const int b   = blockIdx.y;
    const int tid = threadIdx.x;
    const int w   = tid >> 5;
    const int l   = tid & 31;
    const int k0  = 2 * w;

    float acc0[CC], acc1[CC];
#pragma unroll
    for (int c = 0; c < CC; ++c) { acc0[c] = 0.0f; acc1[c] = 0.0f; }
    float ssq0 = 0.0f, ssq1 = 0.0f, cnt0 = 0.0f, cnt1 = 0.0f;

    const float* embB  = emb + (size_t)b * CC * HWHW;
    const int*   mB0   = mask + (size_t)b * KK * HWHW + (size_t)k0 * HWHW;
    const int*   mB1   = mB0 + HWHW;

    for (int ch = blockIdx.x; ch < NCHUNK; ch += gridDim.x) {
        const int pix0 = ch * CHUNK;

        __syncthreads();  // protect shared from previous iteration's readers

        // ---- stage 16 x 256 floats of emb into shared (float4, coalesced) ----
#pragma unroll
        for (int j = 0; j < 4; ++j) {
            int q  = tid + j * NTHREADS;   // 0..1023
            int c  = q >> 6;               // channel
            int pi = q & 63;               // float4 index within chunk
            float4 v = *(const float4*)(embB + (size_t)c * HWHW + pix0 + pi * 4);
            ((float4*)emb_sh[c])[pi] = v;
        }
        __syncthreads();

        // ---- precompute s2[p] = sum_c e^2 once per pixel ----
        {
            int p = tid;
            float s = 0.0f;
#pragma unroll
            for (int c = 0; c < CC; ++c) { float e = emb_sh[c][p]; s = fmaf(e, e, s); }
            s2_sh[p] = s;
        }
        __syncthreads();

        // ---- each warp accumulates its two masks over the 256-pixel chunk ----
#pragma unroll
        for (int it = 0; it < CHUNK / 128; ++it) {
            const int p4 = it * 32 + l;    // float4 / int4 index
            int4 m0 = *(const int4*)(mB0 + pix0 + p4 * 4);
            int4 m1 = *(const int4*)(mB1 + pix0 + p4 * 4);
            float f0x = (m0.x != 0) ? 1.0f : 0.0f;
            float f0y = (m0.y != 0) ? 1.0f : 0.0f;
            float f0z = (m0.z != 0) ? 1.0f : 0.0f;
            float f0w = (m0.w != 0) ? 1.0f : 0.0f;
            float f1x = (m1.x != 0) ? 1.0f : 0.0f;
            float f1y = (m1.y != 0) ? 1.0f : 0.0f;
            float f1z = (m1.z != 0) ? 1.0f : 0.0f;
            float f1w = (m1.w != 0) ? 1.0f : 0.0f;

            float4 s2v = ((const float4*)s2_sh)[p4];
#pragma unroll
            for (int c = 0; c < CC; ++c) {
                float4 e = ((const float4*)emb_sh[c])[p4];
                acc0[c] = fmaf(e.x, f0x, acc0[c]);
                acc0[c] = fmaf(e.y, f0y, acc0[c]);
                acc0[c] = fmaf(e.z, f0z, acc0[c]);
                acc0[c] = fmaf(e.w, f0w, acc0[c]);
                acc1[c] = fmaf(e.x, f1x, acc1[c]);
                acc1[c] = fmaf(e.y, f1y, acc1[c]);
                acc1[c] = fmaf(e.z, f1z, acc1[c]);
                acc1[c] = fmaf(e.w, f1w, acc1[c]);
            }
            ssq0 = fmaf(s2v.x, f0x, ssq0);
            ssq0 = fmaf(s2v.y, f0y, ssq0);
            ssq0 = fmaf(s2v.z, f0z, ssq0);
            ssq0 = fmaf(s2v.w, f0w, ssq0);
            ssq1 = fmaf(s2v.x, f1x, ssq1);
            ssq1 = fmaf(s2v.y, f1y, ssq1);
            ssq1 = fmaf(s2v.z, f1z, ssq1);
            ssq1 = fmaf(s2v.w, f1w, ssq1);
            cnt0 += (f0x + f0y) + (f0z + f0w);
            cnt1 += (f1x + f1y) + (f1z + f1w);
        }
    }

    // ---- warp reduction and global accumulation ----
#pragma unroll
    for (int c = 0; c < CC; ++c) {
        acc0[c] = warp_sum(acc0[c]);
        acc1[c] = warp_sum(acc1[c]);
    }
    ssq0 = warp_sum(ssq0);
    ssq1 = warp_sum(ssq1);
    cnt0 = warp_sum(cnt0);
    cnt1 = warp_sum(cnt1);

    if (l == 0) {
#pragma unroll
        for (int c = 0; c < CC; ++c) {
            atomicAdd(&g_stats[b][k0][c],     acc0[c]);
            atomicAdd(&g_stats[b][k0 + 1][c], acc1[c]);
        }
        atomicAdd(&g_stats[b][k0][16],     ssq0);
        atomicAdd(&g_stats[b][k0][17],     cnt0);
        atomicAdd(&g_stats[b][k0 + 1][16], ssq1);
        atomicAdd(&g_stats[b][k0 + 1][17], cnt1);
    }
}

__global__ void loss_kernel(float* __restrict__ out) {
    __shared__ float sh_means[BB][KK][CC];
    __shared__ float sh_pull[BB][KK];
    __shared__ float sh_valid[BB][KK];
    __shared__ float sh_push[BB];
    __shared__ float sh_pullb[BB];
    __shared__ float sh_M[BB];

    const int t = threadIdx.x;
    if (t < BB) sh_push[t] = 0.0f;

    if (t < BB * KK) {
        int b = t >> 4, k = t & 15;
        const float* s = g_stats[b][k];
        float cnt = s[17];
        float ssq = s[16];
        bool valid = cnt > 0.0f;
        float safe = fmaxf(cnt, 1.0f);
        float inv = 1.0f / safe;
        float dot = 0.0f;
#pragma unroll
        for (int c = 0; c < CC; ++c) {
            float sv = s[c];
            float m = sv * inv;
            sh_means[b][k][c] = m;
            dot = fmaf(sv, m, dot);
        }
        // pull numerator = ssq - 2*mean.sum + cnt*mean^2 summed over c = ssq - dot (when valid)
        sh_pull[b][k]  = valid ? (ssq - dot) / (cnt + 1e-6f) : 0.0f;
        sh_valid[b][k] = valid ? 1.0f : 0.0f;
    }
    __syncthreads();

    if (t < BB) {
        float M = 0.0f, ps = 0.0f;
        for (int k = 0; k < KK; ++k) { M += sh_valid[t][k]; ps += sh_pull[t][k]; }
        sh_M[t]     = M;
        sh_pullb[t] = ps / fmaxf(M, 1.0f);
    }

    // pairwise push: iterate full 16x16 grid per b, keep i<j
    float local0 = 0.0f, local1 = 0.0f, local2 = 0.0f, local3 = 0.0f;
    for (int idx = t; idx < BB * KK * KK; idx += blockDim.x) {
        int b = idx >> 8;
        int ij = idx & 255;
        int i = ij >> 4, j = ij & 15;
        if (i < j && sh_valid[b][i] > 0.0f && sh_valid[b][j] > 0.0f) {
            float d2 = 0.0f;
#pragma unroll
            for (int c = 0; c < CC; ++c) {
                float d = sh_means[b][i][c] - sh_means[b][j][c];
                d2 = fmaf(d, d, d2);
            }
            float dist = sqrtf(d2 + 1e-12f);
            float tm = fmaxf(1.5f - dist, 0.0f);
            float t2 = tm * tm;
            if (b == 0) local0 += t2;
            else if (b == 1) local1 += t2;
            else if (b == 2) local2 += t2;
            else local3 += t2;
        }
    }
    if (local0 != 0.0f) atomicAdd(&sh_push[0], local0);
    if (local1 != 0.0f) atomicAdd(&sh_push[1], local1);
    if (local2 != 0.0f) atomicAdd(&sh_push[2], local2);
    if (local3 != 0.0f) atomicAdd(&sh_push[3], local3);
    __syncthreads();

    if (t == 0) {
        float loss = 0.0f;
        for (int b = 0; b < BB; ++b) {
            float M = sh_M[b];
            float npairs = M * (M - 1.0f) * 0.5f;
            float push = (M > 1.0f) ? sh_push[b] / fmaxf(npairs, 1.0f) : 0.0f;
            loss += 0.5f * sh_pullb[b] + push;   // DELTA_PULL = 0.5
        }
        out[0] = loss * (1.0f / BB);
    }
}

extern "C" void kernel_launch(void* const* d_in, const int* in_sizes, int n_in,
                              void* d_out, int out_size) {
    const float* emb  = (const float*)d_in[0];
    const int*   mask = (const int*)d_in[1];
    float* out = (float*)d_out;

    zero_stats_kernel<<<(BB * KK * 18 + 255) / 256, 256>>>();
    dim3 grid(GRIDX, BB);
    stats_kernel<<<grid, NTHREADS>>>(emb, mask);
    loss_kernel<<<1, 128>>>(out);
}

// round 2
// speedup vs baseline: 1.0960x; 1.0960x over previous
#include <cuda_runtime.h>
#include <cuda_bf16.h>
#include <cstdint>

#define BB 4
#define CC 16
#define KK 16
#define HWHW (512 * 512)          // 262144
#define CHUNK 256
#define NCHUNK (HWHW / CHUNK)     // 1024
#define GRIDX 148
#define NTH 128
#define KPW 4                     // k's per warp (4 warps x 4 = 16)

#define EMB_BUF_FLOATS (CC * CHUNK)   // 4096 floats = 16 KB
#define MSK_BUF_INTS   (KK * CHUNK)   // 4096 ints   = 16 KB
#define SMEM_BYTES (2 * (EMB_BUF_FLOATS * 4 + MSK_BUF_INTS * 4))  // 65536

// stats per (b,k): [0..15] channel sums, [16] sum ||e||^2 over fg, [17] count
__device__ float g_stats[BB][KK][18];   // zero-initialized at module load; re-zeroed by loss_kernel

// ---------------- f32x2 helpers ----------------
__device__ __forceinline__ unsigned long long pack2(float lo, float hi) {
    unsigned long long r;
    asm("mov.b64 %0, {%1, %2};" : "=l"(r) : "f"(lo), "f"(hi));
    return r;
}
__device__ __forceinline__ void fma2(unsigned long long& acc, unsigned long long a, unsigned long long b) {
    asm("fma.rn.f32x2 %0, %1, %2, %3;" : "=l"(acc) : "l"(a), "l"(b), "l"(acc));
}
__device__ __forceinline__ void add2(unsigned long long& acc, unsigned long long a) {
    asm("add.rn.f32x2 %0, %1, %2;" : "=l"(acc) : "l"(acc), "l"(a));
}
__device__ __forceinline__ float unpack_sum(unsigned long long v) {
    float lo, hi;
    asm("mov.b64 {%0, %1}, %2;" : "=f"(lo), "=f"(hi) : "l"(v));
    return lo + hi;
}
__device__ __forceinline__ float warp_sum(float x) {
#pragma unroll
    for (int off = 16; off > 0; off >>= 1)
        x += __shfl_down_sync(0xffffffffu, x, off);
    return x;
}
__device__ __forceinline__ void cp_async16(uint32_t dst_smem, const void* src) {
    asm volatile("cp.async.cg.shared.global [%0], [%1], 16;" :: "r"(dst_smem), "l"(src) : "memory");
}

// ---------------- stats kernel ----------------
__global__ __launch_bounds__(NTH, 2)
void stats_kernel(const float* __restrict__ emb, const int* __restrict__ mask) {
    extern __shared__ char smraw[];
    float* embs = (float*)smraw;                                   // [2][CC][CHUNK]
    int*   msks = (int*)(smraw + 2 * EMB_BUF_FLOATS * 4);          // [2][KK][CHUNK]

    const int b   = blockIdx.y;
    const int bx  = blockIdx.x;
    const int tid = threadIdx.x;
    const int w   = tid >> 5;
    const int l   = tid & 31;

    const float* embB = emb  + (size_t)b * CC * HWHW;
    const int*   mskB = mask + (size_t)b * KK * HWHW;

    unsigned long long acc[KPW][CC];
    unsigned long long ssq[KPW], cnt[KPW];
#pragma unroll
    for (int kk = 0; kk < KPW; ++kk) {
#pragma unroll
        for (int c = 0; c < CC; ++c) acc[kk][c] = 0ull;
        ssq[kk] = 0ull; cnt[kk] = 0ull;
    }

    auto prefetch = [&](int buf, int ch) {
        if (ch < NCHUNK) {
            const int pix0 = ch * CHUNK;
            uint32_t se = (uint32_t)__cvta_generic_to_shared(embs + buf * EMB_BUF_FLOATS);
            uint32_t sk = (uint32_t)__cvta_generic_to_shared(msks + buf * MSK_BUF_INTS);
            // 1024 16B units for emb (64 per channel), 1024 for mask
#pragma unroll
            for (int j = 0; j < 8; ++j) {
                int u   = tid + j * NTH;         // 0..1023
                int c   = u >> 6;
                int off = (u & 63) << 2;         // float offset
                cp_async16(se + (uint32_t)(c * CHUNK + off) * 4,
                           embB + (size_t)c * HWHW + pix0 + off);
            }
#pragma unroll
            for (int j = 0; j < 8; ++j) {
                int u   = tid + j * NTH;
                int k   = u >> 6;
                int off = (u & 63) << 2;
                cp_async16(sk + (uint32_t)(k * CHUNK + off) * 4,
                           mskB + (size_t)k * HWHW + pix0 + off);
            }
        }
        asm volatile("cp.async.commit_group;" ::: "memory");
    };

    prefetch(0, bx);
    prefetch(1, bx + GRIDX);

    int i = 0;
    for (int ch = bx; ch < NCHUNK; ch += GRIDX, ++i) {
        asm volatile("cp.async.wait_group 1;" ::: "memory");
        __syncthreads();
        const int buf = i & 1;
        const float* eb = embs + buf * EMB_BUF_FLOATS;
        const int*   mb = msks + buf * MSK_BUF_INTS;

#pragma unroll
        for (int it = 0; it < CHUNK / 128; ++it) {
            const int p4 = it * 32 + l;   // float4/int4 index (0..63)

            unsigned long long fA[KPW], fB[KPW];
#pragma unroll
            for (int kk = 0; kk < KPW; ++kk) {
                int4 m = ((const int4*)(mb + (w * KPW + kk) * CHUNK))[p4];
                fA[kk] = pack2(m.x > 0 ? 1.0f : 0.0f, m.y > 0 ? 1.0f : 0.0f);
                fB[kk] = pack2(m.z > 0 ? 1.0f : 0.0f, m.w > 0 ? 1.0f : 0.0f);
            }

            unsigned long long s2A = 0ull, s2B = 0ull;
#pragma unroll
            for (int c = 0; c < CC; ++c) {
                ulonglong2 ev = ((const ulonglong2*)(eb + c * CHUNK))[p4];
                fma2(s2A, ev.x, ev.x);
                fma2(s2B, ev.y, ev.y);
#pragma unroll
                for (int kk = 0; kk < KPW; ++kk) {
                    fma2(acc[kk][c], ev.x, fA[kk]);
                    fma2(acc[kk][c], ev.y, fB[kk]);
                }
            }
#pragma unroll
            for (int kk = 0; kk < KPW; ++kk) {
                fma2(ssq[kk], s2A, fA[kk]);
                fma2(ssq[kk], s2B, fB[kk]);
                add2(cnt[kk], fA[kk]);
                add2(cnt[kk], fB[kk]);
            }
        }
        __syncthreads();
        prefetch(buf, ch + 2 * GRIDX);
    }

    // warp reduce + global accumulate
#pragma unroll
    for (int kk = 0; kk < KPW; ++kk) {
        const int k = w * KPW + kk;
#pragma unroll
        for (int c = 0; c < CC; ++c) {
            float v = warp_sum(unpack_sum(acc[kk][c]));
            if (l == 0) atomicAdd(&g_stats[b][k][c], v);
        }
        float s = warp_sum(unpack_sum(ssq[kk]));
        float n = warp_sum(unpack_sum(cnt[kk]));
        if (l == 0) {
            atomicAdd(&g_stats[b][k][16], s);
            atomicAdd(&g_stats[b][k][17], n);
        }
    }
}

// ---------------- loss kernel (also re-zeroes stats for next graph replay) ----------------
__global__ void loss_kernel(float* __restrict__ out) {
    __shared__ float sh_means[BB][KK][CC];
    __shared__ float sh_pull[BB][KK];
    __shared__ float sh_valid[BB][KK];
    __shared__ float sh_push[BB];
    __shared__ float sh_pullb[BB];
    __shared__ float sh_M[BB];

    const int t = threadIdx.x;
    if (t < BB) sh_push[t] = 0.0f;

    if (t < BB * KK) {
        int b = t >> 4, k = t & 15;
        const float* s = g_stats[b][k];
        float cnt = s[17];
        float ssq = s[16];
        bool valid = cnt > 0.0f;
        float inv = 1.0f / fmaxf(cnt, 1.0f);
        float dot = 0.0f;
#pragma unroll
        for (int c = 0; c < CC; ++c) {
            float sv = s[c];
            float m = sv * inv;
            sh_means[b][k][c] = m;
            dot = fmaf(sv, m, dot);
        }
        sh_pull[b][k]  = valid ? (ssq - dot) / (cnt + 1e-6f) : 0.0f;
        sh_valid[b][k] = valid ? 1.0f : 0.0f;
    }
    __syncthreads();

    // all g_stats reads are done -> re-zero for the next launch/replay
    for (int i = t; i < BB * KK * 18; i += blockDim.x)
        ((float*)g_stats)[i] = 0.0f;

    if (t < BB) {
        float M = 0.0f, ps = 0.0f;
        for (int k = 0; k < KK; ++k) { M += sh_valid[t][k]; ps += sh_pull[t][k]; }
        sh_M[t]     = M;
        sh_pullb[t] = ps / fmaxf(M, 1.0f);
    }

    float local[BB] = {0.0f, 0.0f, 0.0f, 0.0f};
    for (int idx = t; idx < BB * KK * KK; idx += blockDim.x) {
        int b = idx >> 8;
        int ij = idx & 255;
        int i = ij >> 4, j = ij & 15;
        if (i < j && sh_valid[b][i] > 0.0f && sh_valid[b][j] > 0.0f) {
            float d2 = 0.0f;
#pragma unroll
            for (int c = 0; c < CC; ++c) {
                float d = sh_means[b][i][c] - sh_means[b][j][c];
                d2 = fmaf(d, d, d2);
            }
            float dist = sqrtf(d2 + 1e-12f);
            float tm = fmaxf(1.5f - dist, 0.0f);
            local[b] += tm * tm;
        }
    }
#pragma unroll
    for (int b = 0; b < BB; ++b)
        if (local[b] != 0.0f) atomicAdd(&sh_push[b], local[b]);
    __syncthreads();

    if (t == 0) {
        float loss = 0.0f;
        for (int b = 0; b < BB; ++b) {
            float M = sh_M[b];
            float npairs = M * (M - 1.0f) * 0.5f;
            float push = (M > 1.0f) ? sh_push[b] / fmaxf(npairs, 1.0f) : 0.0f;
            loss += 0.5f * sh_pullb[b] + push;   // DELTA_PULL = 0.5
        }
        out[0] = loss * (1.0f / BB);
    }
}

extern "C" void kernel_launch(void* const* d_in, const int* in_sizes, int n_in,
                              void* d_out, int out_size) {
    const float* emb  = (const float*)d_in[0];
    const int*   mask = (const int*)d_in[1];
    float* out = (float*)d_out;

    cudaFuncSetAttribute(stats_kernel, cudaFuncAttributeMaxDynamicSharedMemorySize, SMEM_BYTES);

    dim3 grid(GRIDX, BB);
    stats_kernel<<<grid, NTH, SMEM_BYTES>>>(emb, mask);
    loss_kernel<<<1, 128>>>(out);
}